// round 2
// baseline (speedup 1.0000x reference)
#include <cuda_runtime.h>
#include <cuda_bf16.h>
#include <math.h>

// ---------------- problem constants ----------------
#define NN      65536
#define ROWS    16      // BATCH*CH
#define JLEV    5
#define QQ      8
#define CQ      32      // QQ*CH
#define TT      15
#define OUTN    16384   // NN/4
#define OUTCH   160     // JLEV*CQ

typedef unsigned long long ull;

// ---------------- wavelet filters ----------------
__constant__ float c_H0O[13] = {
  -0.00455690456024f, -0.00543947593727f,  0.01702522388155f,  0.02382538479492f,
  -0.10671180468666f,  0.01186609203379f,  0.56881042071212f,  0.75614564389252f,
   0.27529538466888f, -0.11720388769911f, -0.03887280126882f,  0.03466034684485f,
  -0.00388321199915f };
__constant__ float c_H1O[13] = {
  -0.00388321199915f, -0.03466034684485f, -0.03887280126882f,  0.11720388769911f,
   0.27529538466888f, -0.75614564389252f,  0.56881042071212f, -0.01186609203379f,
  -0.10671180468666f, -0.02382538479492f,  0.01702522388155f,  0.00543947593727f,
  -0.00455690456024f };
__constant__ float c_H0A[10] = {
   0.03516384f, 0.0f, -0.08832942f, 0.23389032f, 0.76027237f,
   0.58751830f, 0.0f, -0.11430184f, 0.0f, 0.0f };
__constant__ float c_H0B[10] = {
   0.0f, 0.0f, -0.11430184f, 0.0f, 0.58751830f,
   0.76027237f, 0.23389032f, -0.08832942f, 0.0f, 0.03516384f };
__constant__ float c_H1A[10] = {
   0.0f, 0.0f, -0.11430184f, 0.0f, 0.58751830f,
  -0.76027237f, 0.23389032f, 0.08832942f, 0.0f, -0.03516384f };
__constant__ float c_H1B[10] = {
  -0.03516384f, 0.0f, 0.08832942f, 0.23389032f, -0.76027237f,
   0.58751830f, 0.0f, -0.11430184f, 0.0f, 0.0f };

// ---------------- scratch: interleaved (r,i) bandpass ----------------
__device__ float2 g_bp[(size_t)JLEV * ROWS * NN];

// ---------------- packed f32x2 helpers ----------------
__device__ __forceinline__ ull pack2(float x, float y) {
  ull r; asm("mov.b64 %0, {%1, %2};" : "=l"(r) : "f"(x), "f"(y)); return r;
}
__device__ __forceinline__ void unpack2(ull v, float& x, float& y) {
  asm("mov.b64 {%0, %1}, %2;" : "=f"(x), "=f"(y) : "l"(v));
}
__device__ __forceinline__ ull ffma2(ull a, ull b, ull c) {
  ull d; asm("fma.rn.f32x2 %0, %1, %2, %3;" : "=l"(d) : "l"(a), "l"(b), "l"(c));
  return d;
}

// ---------------- kernel 1: undecimated dual-tree CWT ----------------
#define TILE_W 2048
#define HALO   80
#define EXT    (TILE_W + 2*HALO)   // 2208

template<int D, int M>
__device__ __forceinline__ void tree_level(
    const float* la, const float* lb,
    float* la_n, float* lb_n,
    float2* __restrict__ bp)
{
  const int PAD = (D * 9) / 2;
  for (int i = threadIdx.x; i < TILE_W; i += 256) {
    const int s = HALO + i;
    float ar = 0.f, ai = 0.f;
#pragma unroll
    for (int k = 0; k < 10; k++) {
      ar = fmaf(c_H1A[k], la[s + D*k - PAD], ar);
      ai = fmaf(c_H1B[k], lb[s + D*k - PAD], ai);
    }
    bp[i] = make_float2(ar, ai);
  }
  if (la_n != nullptr) {
    for (int i = threadIdx.x; i < TILE_W + 2*M; i += 256) {
      const int s = HALO - M + i;
      float a = 0.f, b = 0.f;
#pragma unroll
      for (int k = 0; k < 10; k++) {
        a = fmaf(c_H0A[k], la[s + D*k - PAD], a);
        b = fmaf(c_H0B[k], lb[s + D*k - PAD], b);
      }
      la_n[s] = a; lb_n[s] = b;
    }
  }
}

__global__ __launch_bounds__(256) void udtcwt_kernel(const float* __restrict__ x)
{
  __shared__ float sA[EXT], sB[EXT], sC[EXT], sD[EXT];
  const int row = blockIdx.y;
  const int t0  = blockIdx.x * TILE_W;
  const float* xr = x + (size_t)row * NN;

  for (int s = threadIdx.x; s < EXT; s += 256) {
    const int g = t0 - HALO + s;
    sA[s] = (g >= 0 && g < NN) ? xr[g] : 0.f;
  }
  __syncthreads();

  // level 0: 13-tap near_sym_b, both trees identical
  {
    float2* outp = g_bp + ((size_t)(0*ROWS + row)) * NN + t0;
    for (int i = threadIdx.x; i < TILE_W; i += 256) {
      const int s = HALO + i;
      float acc = 0.f;
#pragma unroll
      for (int k = 0; k < 13; k++) acc = fmaf(c_H1O[k], sA[s + k - 6], acc);
      outp[i] = make_float2(acc, acc);
    }
    for (int i = threadIdx.x; i < TILE_W + 2*68; i += 256) {
      const int s = HALO - 68 + i;
      float acc = 0.f;
#pragma unroll
      for (int k = 0; k < 13; k++) acc = fmaf(c_H0O[k], sA[s + k - 6], acc);
      sB[s] = acc;
    }
  }
  __syncthreads();

  tree_level<1, 63>(sB, sB, sC, sD, g_bp + ((size_t)(1*ROWS + row))*NN + t0);
  __syncthreads();
  tree_level<2, 54>(sC, sD, sA, sB, g_bp + ((size_t)(2*ROWS + row))*NN + t0);
  __syncthreads();
  tree_level<4, 36>(sA, sB, sC, sD, g_bp + ((size_t)(3*ROWS + row))*NN + t0);
  __syncthreads();
  tree_level<8, 0>(sC, sD, (float*)nullptr, (float*)nullptr,
                   g_bp + ((size_t)(4*ROWS + row))*NN + t0);
}

// ---------------- kernel 2: phase-decomposed gconv+mod+pow+down4 ----------------
// out[n] = sum_{m=0}^{36} g[m] * u[4n + m - 18]   (two lowpass+::2 stages fused)
// u[t] = (sqrt(r^2+i^2)/2^{j/2} + beta)^sigmoid(root),  r/i = 15-tap dilated conv.
#define TOX   1024
#define ULEN  (4*TOX + 33)   // 4129
#define UPAD  (4*TOX + 48)   // 4144 (float4 read padding)

template<int D>
__global__ __launch_bounds__(256, 2) void scatter(
    const float* __restrict__ conv_w, const float* __restrict__ roots,
    const float* __restrict__ beta_p, float* __restrict__ out, int jbase)
{
  constexpr int SU     = (ULEN + D - 1) / D;   // u's per phase
  constexpr int CP     = (SU + 3) / 4;         // 4-u chunks per phase
  constexpr int CHUNKS = D * CP;
  constexpr int SLEN   = 4 * CP + 18;          // bp samples needed per phase (+margin)
  constexpr int SP     = (SLEN + 1) & ~1;      // even stride (16B-aligned phases)

  __shared__ float2 s_bp[D * SP];
  __shared__ float  s_u[UPAD];
  __shared__ float  s_w[QQ * TT];
  __shared__ float  s_g[40];
  __shared__ float  s_alpha[QQ];

  const int j   = jbase + blockIdx.z;
  const int row = blockIdx.y;              // b*CH + c
  const int b   = row >> 2, c = row & 3;
  const int o0  = blockIdx.x * TOX;
  const float inv_scale = exp2f(-0.5f * (float)j);
  const float beta = beta_p[0];

  const int tmin = 4 * o0 - 18;
  const int pmin = tmin - 7 * D;

  const float2* bp = g_bp + ((size_t)(j * ROWS + row)) * NN;

  // ---- fill phase-separated bp tile ----
  for (int i = threadIdx.x; i < D * SP; i += 256) {
    const int p = i % D, s = i / D;
    const int gi = pmin + i;
    s_bp[p * SP + s] = (gi >= 0 && gi < NN) ? bp[gi] : make_float2(0.f, 0.f);
  }
  if (threadIdx.x < 37) {                  // composite /4 downsample filter
    const int m = threadIdx.x;
    float acc = 0.f;
    for (int k = 0; k < 13; k++) {
      const int kp = m - 2 * k;
      if (kp >= 0 && kp < 13) acc += c_H0O[k] * c_H0O[kp];
    }
    s_g[m] = acc;
  }
  for (int i = threadIdx.x; i < QQ * TT; i += 256) {
    const int q = i / TT, k = i % TT;
    s_w[i] = conv_w[(size_t)(j * CQ + c * QQ + q) * TT + k];
  }
  if (threadIdx.x < QQ) {
    const float rt = roots[j * CQ + c * QQ + threadIdx.x];
    s_alpha[threadIdx.x] = 1.f / (1.f + __expf(-rt));
  }
  __syncthreads();

  for (int q = 0; q < QQ; q++) {
    ull w2[TT];
#pragma unroll
    for (int k = 0; k < TT; k++) { const float wv = s_w[q * TT + k]; w2[k] = pack2(wv, wv); }
    const float alpha = s_alpha[q];

    // ---- u computation: 4 consecutive-in-phase u's per chunk ----
    for (int m = threadIdx.x; m < CHUNKS; m += 256) {
      const int p = m % D, cc = m / D;
      const float4* vp = reinterpret_cast<const float4*>(s_bp) + (size_t)p * (SP / 2) + 2 * cc;
      ull v[18];
#pragma unroll
      for (int t = 0; t < 9; t++) {
        const float4 qv = vp[t];
        v[2*t]   = pack2(qv.x, qv.y);
        v[2*t+1] = pack2(qv.z, qv.w);
      }
      const int s0 = 4 * cc;
#pragma unroll
      for (int r = 0; r < 4; r++) {
        const int ui = p + D * (s0 + r);
        if (ui < ULEN) {
          ull acc = pack2(0.f, 0.f);
#pragma unroll
          for (int k = 0; k < TT; k++) acc = ffma2(w2[k], v[k + r], acc);
          float rr, ii; unpack2(acc, rr, ii);
          const int t = tmin + ui;
          float u = 0.f;
          if (t >= 0 && t < NN) {
            const float hyp = sqrtf(fmaf(rr, rr, ii * ii)) * inv_scale;
            u = exp2f(alpha * __log2f(hyp + beta));
          }
          s_u[ui] = u;
        }
      }
    }
    __syncthreads();

    // ---- fused 37-tap stride-4 downsample: 4 outputs/thread ----
    {
      const float4* su4 = reinterpret_cast<const float4*>(s_u) + 4 * threadIdx.x;
      float a[52];
      const int rot = (threadIdx.x >> 1) & 3;
#pragma unroll
      for (int tt = 0; tt < 13; tt++) {
        int t = tt + rot; if (t >= 13) t -= 13;
        const float4 qv = su4[t];
        a[4*t] = qv.x; a[4*t+1] = qv.y; a[4*t+2] = qv.z; a[4*t+3] = qv.w;
      }
      float4 o;
      float* op = &o.x;
#pragma unroll
      for (int r = 0; r < 4; r++) {
        float acc = 0.f;
#pragma unroll
        for (int mm = 0; mm < 37; mm++) acc = fmaf(s_g[mm], a[4*r + mm], acc);
        op[r] = acc;
      }
      float* dst = out + ((size_t)(b * OUTCH + j * CQ + c * QQ + q)) * OUTN
                       + o0 + 4 * threadIdx.x;
      *reinterpret_cast<float4*>(dst) = o;
    }
    __syncthreads();
  }
}

// ---------------- launch ----------------
extern "C" void kernel_launch(void* const* d_in, const int* in_sizes, int n_in,
                              void* d_out, int out_size)
{
  const float* x      = (const float*)d_in[0];
  const float* conv_w = (const float*)d_in[1];
  const float* roots  = (const float*)d_in[2];
  const float* beta   = (const float*)d_in[3];
  float* out = (float*)d_out;

  dim3 gW(NN / TILE_W, ROWS);                 // 32 x 16
  udtcwt_kernel<<<gW, 256>>>(x);

  dim3 g1(OUTN / TOX, ROWS, 2);               // j = 0,1 (d=1)
  scatter<1><<<g1, 256>>>(conv_w, roots, beta, out, 0);
  dim3 g2(OUTN / TOX, ROWS, 1);
  scatter<2><<<g2, 256>>>(conv_w, roots, beta, out, 2);   // j = 2
  scatter<4><<<g2, 256>>>(conv_w, roots, beta, out, 3);   // j = 3
  scatter<8><<<g2, 256>>>(conv_w, roots, beta, out, 4);   // j = 4
}